// round 15
// baseline (speedup 1.0000x reference)
#include <cuda_runtime.h>
#include <cuda_fp16.h>

#define N_NODES 50000
#define N_EDGES 800000
#define IN_C    16
#define OUT_C   16
#define EDGE_F  8

// y table in fp16, bias block SEPARATED:
//   g_yh16: per node 8 edge-feature blocks x 16 outputs = 16 uint4 = 256 B
//           = exactly 2 cache lines (128B-aligned). slot j = f*2 + h.
//   g_yb:   per node bias block (f=8) = 2 uint4; gathered only if b_nn != 0.
#define YSTRIDE 16

#define NPAIR (N_NODES / 2)      // 25000 node-pairs (strided)

__device__ __align__(128) uint4 g_yh16[N_NODES * YSTRIDE];  // 12.8 MB
__device__ __align__(16)  uint4 g_yb[N_NODES * 2];          // 1.6 MB
__device__ int g_bias_nz;        // 1 iff any b_nn element nonzero

// ---------------------------------------------------------------------------
// Kernel A: per-node precompute, 2-node register blocking (R14 winner),
// writing the split tables. Block 0 reduces b_nn into g_bias_nz inline.
// ---------------------------------------------------------------------------
__global__ void node_kernel(const float* __restrict__ x,
                            const float* __restrict__ w_nn,
                            const float* __restrict__ b_nn,
                            const float* __restrict__ root,
                            const float* __restrict__ bias,
                            float* __restrict__ out)
{
    __shared__ float Wsh[9 * 256];      // [f][i*16+o], f==8 holds b_nn
    __shared__ float Rsh[256 + 16];     // root [i][o] + bias[o]

    for (int t = threadIdx.x; t < 2048; t += blockDim.x) Wsh[t] = w_nn[t];
    for (int t = threadIdx.x; t < 256;  t += blockDim.x) Wsh[2048 + t] = b_nn[t];
    for (int t = threadIdx.x; t < 256;  t += blockDim.x) Rsh[t] = root[t];
    for (int t = threadIdx.x; t < 16;   t += blockDim.x) Rsh[256 + t] = bias[t];
    __syncthreads();

    // ---- inline bias flag (block 0 only, piggybacks on staged smem) ----
    if (blockIdx.x == 0) {
        int v = (threadIdx.x < 256) ? (Wsh[2048 + threadIdx.x] != 0.0f) : 0;
        v = __syncthreads_or(v);
        if (threadIdx.x == 0) g_bias_nz = v;
    }

    const int gsz  = gridDim.x * blockDim.x;
    const int tid0 = blockIdx.x * blockDim.x + threadIdx.x;

    for (int t = tid0; t < NPAIR * 2; t += gsz) {      // 50000 tasks
        const int grp = t >> 1;
        const int h   = t & 1;                 // outputs h*8 .. h*8+7

        // ---- load x for 2 strided nodes into registers ----
        float xv[2][16];
        #pragma unroll
        for (int k = 0; k < 2; k++) {
            const int n = grp + k * NPAIR;
            const float4* xr = (const float4*)(x + n * IN_C);
            #pragma unroll
            for (int ii = 0; ii < 4; ii++) {
                float4 xx = xr[ii];
                xv[k][4*ii+0] = xx.x; xv[k][4*ii+1] = xx.y;
                xv[k][4*ii+2] = xx.z; xv[k][4*ii+3] = xx.w;
            }
        }

        // ---- 9 blocks: f=0..7 -> g_yh16, f=8 (bias) -> g_yb ----
        #pragma unroll
        for (int f = 0; f < 9; f++) {
            float acc[2][8];
            #pragma unroll
            for (int k = 0; k < 2; k++)
                #pragma unroll
                for (int o = 0; o < 8; o++) acc[k][o] = 0.f;

            const float* wb = &Wsh[f * 256 + h * 8];
            #pragma unroll
            for (int i = 0; i < 16; i++) {
                const float4 wlo = *(const float4*)(wb + i * 16);
                const float4 whi = *(const float4*)(wb + i * 16 + 4);
                const float w[8] = {wlo.x, wlo.y, wlo.z, wlo.w,
                                    whi.x, whi.y, whi.z, whi.w};
                #pragma unroll
                for (int k = 0; k < 2; k++) {
                    const float xi = xv[k][i];
                    #pragma unroll
                    for (int o = 0; o < 8; o++) acc[k][o] += xi * w[o];
                }
            }

            #pragma unroll
            for (int k = 0; k < 2; k++) {
                __half2 hv[4];
                #pragma unroll
                for (int j = 0; j < 4; j++)
                    hv[j] = __floats2half2_rn(acc[k][2*j], acc[k][2*j+1]);
                const int n = grp + k * NPAIR;
                if (f < 8) g_yh16[n * YSTRIDE + f * 2 + h] = *(const uint4*)hv;
                else       g_yb[n * 2 + h]                 = *(const uint4*)hv;
            }
        }

        // ---- fused root-term halves for the 2 nodes ----
        {
            float racc[2][8];
            #pragma unroll
            for (int k = 0; k < 2; k++)
                #pragma unroll
                for (int o = 0; o < 8; o++) racc[k][o] = Rsh[256 + h * 8 + o];

            #pragma unroll
            for (int i = 0; i < 16; i++) {
                const float4 rlo = *(const float4*)&Rsh[i * 16 + h * 8];
                const float4 rhi = *(const float4*)&Rsh[i * 16 + h * 8 + 4];
                const float r[8] = {rlo.x, rlo.y, rlo.z, rlo.w,
                                    rhi.x, rhi.y, rhi.z, rhi.w};
                #pragma unroll
                for (int k = 0; k < 2; k++) {
                    const float xi = xv[k][i];
                    #pragma unroll
                    for (int o = 0; o < 8; o++) racc[k][o] += xi * r[o];
                }
            }

            #pragma unroll
            for (int k = 0; k < 2; k++) {
                const int n = grp + k * NPAIR;
                float4* od = (float4*)(out + n * OUT_C + h * 8);
                od[0] = make_float4(racc[k][0], racc[k][1], racc[k][2], racc[k][3]);
                od[1] = make_float4(racc[k][4], racc[k][5], racc[k][6], racc[k][7]);
            }
        }
    }
}

// ---------------------------------------------------------------------------
// Kernel B: 8 lanes per edge (4 edges/warp), line-granular gather.
//   Lane sub (0..7): slots {sub, sub+8}: h = sub&1, f = sub>>1 and 4+(sub>>1).
//   Each LDG.128 = 8 lanes x 16 B = one 128 B line per edge -> 2 gather
//   wavefronts/edge. Products in packed half2 (HMUL2+HFMA2, no acc init),
//   fp32 shfl reduce, single red.v2 instruction covering the 64 B dst row.
// ---------------------------------------------------------------------------
__global__ void edge_kernel(const int*   __restrict__ ei,
                            const float* __restrict__ ea,
                            float* __restrict__ out,
                            int echo)
{
    const int g   = blockIdx.x * blockDim.x + threadIdx.x;
    const int e   = g >> 3;                 // edge id (grid exact: N_EDGES*8 thr)
    const int sub = g & 7;
    const int s2  = sub >> 1;               // 0..3
    const int hh  = sub & 1;                // output half

    const int bias_nz = g_bias_nz;

    const int src = __ldg(&ei[e]);
    const int dst = __ldg(&ei[N_EDGES + e]);

    // this lane's two coefficients: f = s2 and f = 4+s2
    // (warp pattern: 4 edges x 8 features = 128 B contiguous per instruction)
    const float c0 = __ldg(&ea[e * EDGE_F + s2]);
    const float c1 = __ldg(&ea[e * EDGE_F + 4 + s2]);

    const uint4* yrow = g_yh16 + src * YSTRIDE;
    const uint4 v0 = yrow[sub];        // line 0: (f = s2,   h = hh)
    const uint4 v1 = yrow[8 + sub];    // line 1: (f = 4+s2, h = hh)

    const __half2 c0h = __float2half2_rn(c0);
    const __half2 c1h = __float2half2_rn(c1);

    const __half2* h0 = (const __half2*)&v0;
    const __half2* h1 = (const __half2*)&v1;

    float f[8];
    #pragma unroll
    for (int j = 0; j < 4; j++) {
        __half2 p = __hfma2(h1[j], c1h, __hmul2(h0[j], c0h));
        float2 pf = __half22float2(p);
        f[2*j]   = pf.x;
        f[2*j+1] = pf.y;
    }

    // bias block (f=8, coef 1) — only when b_nn is not identically zero
    if (bias_nz && sub < 2) {
        const uint4 vb = g_yb[src * 2 + sub];
        const __half2* hb = (const __half2*)&vb;
        #pragma unroll
        for (int j = 0; j < 4; j++) {
            float2 p = __half22float2(hb[j]);
            f[2*j]   += p.x;
            f[2*j+1] += p.y;
        }
    }

    // combine the 4 lanes of each h-parity: {0,2,4,6} -> h=0, {1,3,5,7} -> h=1
    #pragma unroll
    for (int o = 0; o < 8; o++)
        f[o] += __shfl_xor_sync(0xffffffffu, f[o], 2);
    #pragma unroll
    for (int o = 0; o < 8; o++)
        f[o] += __shfl_xor_sync(0xffffffffu, f[o], 4);

    // single red.v2 instruction from all 8 lanes covers the 64 B dst row:
    // lane (hh, s2) -> outputs hh*8 + s2*2 .. +1
    {
        float* o = out + dst * OUT_C + hh * 8 + s2 * 2;
        asm volatile("red.global.add.v2.f32 [%0], {%1, %2};"
                     :: "l"(o), "f"(f[s2 * 2]), "f"(f[s2 * 2 + 1])
                     : "memory");
    }

    // ---- echo streaming, riding the DRAM shadow ----
    if (g < 2 * N_EDGES) {
        if (echo & 1)
            out[N_NODES * OUT_C + g] = (float)__ldg(&ei[g]);
        if (echo & 2) {
            float4*       dst4 = (float4*)(out + N_NODES * OUT_C + 2 * N_EDGES);
            const float4* src4 = (const float4*)ea;
            dst4[g] = src4[g];
        }
    }
}

extern "C" void kernel_launch(void* const* d_in, const int* in_sizes, int n_in,
                              void* d_out, int out_size)
{
    const float* x     = (const float*)d_in[0];
    const int*   ei    = (const int*)  d_in[1];
    const float* ea    = (const float*)d_in[2];
    const float* w_nn  = (const float*)d_in[3];
    const float* b_nn  = (const float*)d_in[4];
    const float* root  = (const float*)d_in[5];
    const float* bias  = (const float*)d_in[6];
    float* out = (float*)d_out;

    int echo = 0;
    if (out_size >= N_NODES * OUT_C + 2 * N_EDGES)                        echo |= 1;
    if (out_size >= N_NODES * OUT_C + 2 * N_EDGES + N_EDGES * EDGE_F)     echo |= 2;

    node_kernel<<<196, 256>>>(x, w_nn, b_nn, root, bias, out);
    edge_kernel<<<(N_EDGES * 8) / 256, 256>>>(ei, ea, out, echo);
}

// round 17
// speedup vs baseline: 1.0931x; 1.0931x over previous
#include <cuda_runtime.h>
#include <cuda_fp16.h>

#define N_NODES 50000
#define N_EDGES 800000
#define IN_C    16
#define OUT_C   16
#define EDGE_F  8

// y table in fp16: per node 9 blocks (8 edge-feature + 1 bias) x 16 outputs,
// = 18 uint4, PADDED to 24 uint4 (384 B = 3 cache lines, 128B-aligned).
// uint4 slot j = f*2 + h; as uint2: row = 48, index = f*4 + oq.
#define YSTRIDE 24

#define NGROUP (N_NODES / 4)     // 12500 node-groups of 4 (strided)

__device__ __align__(128) uint4 g_yh[N_NODES * YSTRIDE];   // 19.2 MB
__device__ int g_bias_nz;        // 1 iff any b_nn element nonzero

// ---------------------------------------------------------------------------
// Kernel A: per-node precompute, K=4 node blocking x output-quarter split.
// Thread = (node-group, oq): ALL 9 f-blocks + root, but only 4 outputs.
// Lane-view LDS bytes halved vs K=2 (115 MB -> 3.5 us crossbar floor) while
// keeping 50k threads (2.6 warps/SMSP). Weight reuse per LDS: 4 nodes.
// Block 0 reduces b_nn into g_bias_nz inline (no extra launch).
// ---------------------------------------------------------------------------
__global__ void node_kernel(const float* __restrict__ x,
                            const float* __restrict__ w_nn,
                            const float* __restrict__ b_nn,
                            const float* __restrict__ root,
                            const float* __restrict__ bias,
                            float* __restrict__ out)
{
    __shared__ float Wsh[9 * 256];      // [f][i*16+o], f==8 holds b_nn
    __shared__ float Rsh[256 + 16];     // root [i][o] + bias[o]

    for (int t = threadIdx.x; t < 2048; t += blockDim.x) Wsh[t] = w_nn[t];
    for (int t = threadIdx.x; t < 256;  t += blockDim.x) Wsh[2048 + t] = b_nn[t];
    for (int t = threadIdx.x; t < 256;  t += blockDim.x) Rsh[t] = root[t];
    for (int t = threadIdx.x; t < 16;   t += blockDim.x) Rsh[256 + t] = bias[t];
    __syncthreads();

    // ---- inline bias flag (block 0 only, piggybacks on staged smem) ----
    if (blockIdx.x == 0) {
        int v = (threadIdx.x < 256) ? (Wsh[2048 + threadIdx.x] != 0.0f) : 0;
        v = __syncthreads_or(v);
        if (threadIdx.x == 0) g_bias_nz = v;
    }

    const int gsz  = gridDim.x * blockDim.x;
    const int tid0 = blockIdx.x * blockDim.x + threadIdx.x;

    for (int t = tid0; t < NGROUP * 4; t += gsz) {     // 50000 tasks
        const int grp = t >> 2;
        const int oq  = t & 3;                 // outputs oq*4 .. oq*4+3

        // ---- load x for 4 strided nodes into registers ----
        float xv[4][16];
        #pragma unroll
        for (int k = 0; k < 4; k++) {
            const int n = grp + k * NGROUP;
            const float4* xr = (const float4*)(x + n * IN_C);
            #pragma unroll
            for (int ii = 0; ii < 4; ii++) {
                float4 xx = xr[ii];
                xv[k][4*ii+0] = xx.x; xv[k][4*ii+1] = xx.y;
                xv[k][4*ii+2] = xx.z; xv[k][4*ii+3] = xx.w;
            }
        }

        // ---- 9 y-blocks: one float4 weight LDS per (f,i), reused 4 nodes ----
        uint2* yrow2 = (uint2*)g_yh;
        #pragma unroll
        for (int f = 0; f < 9; f++) {
            float acc[4][4];
            #pragma unroll
            for (int k = 0; k < 4; k++)
                #pragma unroll
                for (int o = 0; o < 4; o++) acc[k][o] = 0.f;

            const float* wb = &Wsh[f * 256 + oq * 4];
            #pragma unroll
            for (int i = 0; i < 16; i++) {
                const float4 w = *(const float4*)(wb + i * 16);
                #pragma unroll
                for (int k = 0; k < 4; k++) {
                    const float xi = xv[k][i];
                    acc[k][0] += xi * w.x;
                    acc[k][1] += xi * w.y;
                    acc[k][2] += xi * w.z;
                    acc[k][3] += xi * w.w;
                }
            }

            #pragma unroll
            for (int k = 0; k < 4; k++) {
                __half2 hv[2];
                hv[0] = __floats2half2_rn(acc[k][0], acc[k][1]);
                hv[1] = __floats2half2_rn(acc[k][2], acc[k][3]);
                const int n = grp + k * NGROUP;
                yrow2[n * (YSTRIDE * 2) + f * 4 + oq] = *(const uint2*)hv;
            }
        }

        // ---- fused root-term quarters for the 4 nodes ----
        {
            float racc[4][4];
            #pragma unroll
            for (int k = 0; k < 4; k++)
                #pragma unroll
                for (int o = 0; o < 4; o++) racc[k][o] = Rsh[256 + oq * 4 + o];

            #pragma unroll
            for (int i = 0; i < 16; i++) {
                const float4 r = *(const float4*)&Rsh[i * 16 + oq * 4];
                #pragma unroll
                for (int k = 0; k < 4; k++) {
                    const float xi = xv[k][i];
                    racc[k][0] += xi * r.x;
                    racc[k][1] += xi * r.y;
                    racc[k][2] += xi * r.z;
                    racc[k][3] += xi * r.w;
                }
            }

            #pragma unroll
            for (int k = 0; k < 4; k++) {
                const int n = grp + k * NGROUP;
                ((float4*)(out + n * OUT_C))[oq] =
                    make_float4(racc[k][0], racc[k][1], racc[k][2], racc[k][3]);
            }
        }
    }
}

// ---------------------------------------------------------------------------
// Kernel B (verbatim R14 winner): 4 lanes per edge, single red.v4 scatter,
// echo in the DRAM shadow, bias-block gather skipped when b_nn == 0 (exact).
// ---------------------------------------------------------------------------
__global__ void edge_kernel(const int*   __restrict__ ei,
                            const float* __restrict__ ea,
                            float* __restrict__ out,
                            int echo)
{
    const int g   = blockIdx.x * blockDim.x + threadIdx.x;
    const int e   = g >> 2;                 // edge id (grid exact: N_EDGES*4 thr)
    const int sub = g & 3;
    const int s2  = sub >> 1;               // f-parity this lane handles

    const int bias_nz = g_bias_nz;          // uniform, cached after first load

    const int src = __ldg(&ei[e]);
    const int dst = __ldg(&ei[N_EDGES + e]);

    // edge coefficients: lane needs f = s2, s2+2, s2+4, s2+6
    const float4* ea4 = (const float4*)ea;
    const float4 a0 = ea4[2 * e];
    const float4 a1 = ea4[2 * e + 1];
    const float c0 = s2 ? a0.y : a0.x;
    const float c1 = s2 ? a0.w : a0.z;
    const float c2 = s2 ? a1.y : a1.x;
    const float c3 = s2 ? a1.w : a1.z;

    const uint4* yrow = g_yh + src * YSTRIDE;
    const uint4 v0 = yrow[sub];
    const uint4 v1 = yrow[sub + 4];
    const uint4 v2 = yrow[sub + 8];
    const uint4 v3 = yrow[sub + 12];

    float acc[8];
    #pragma unroll
    for (int o = 0; o < 8; o++) acc[o] = 0.f;

    #pragma unroll
    for (int b = 0; b < 4; b++) {
        const uint4  v  = (b == 0) ? v0 : (b == 1) ? v1 : (b == 2) ? v2 : v3;
        const float  cf = (b == 0) ? c0 : (b == 1) ? c1 : (b == 2) ? c2 : c3;
        const __half2* hv = (const __half2*)&v;
        #pragma unroll
        for (int j = 0; j < 4; j++) {
            float2 p = __half22float2(hv[j]);
            acc[2*j]   += cf * p.x;
            acc[2*j+1] += cf * p.y;
        }
    }

    // bias block (f=8, coef 1) — only when b_nn is not identically zero
    if (bias_nz && sub < 2) {
        const uint4 vb = yrow[16 + sub];
        const __half2* hv = (const __half2*)&vb;
        #pragma unroll
        for (int j = 0; j < 4; j++) {
            float2 p = __half22float2(hv[j]);
            acc[2*j]   += p.x;
            acc[2*j+1] += p.y;
        }
    }

    // combine the two f-parities: lane pairs (0,2) and (1,3).
    #pragma unroll
    for (int o = 0; o < 8; o++)
        acc[o] += __shfl_xor_sync(0xffffffffu, acc[o], 2);

    // ONE red.v4 instruction covers the whole 64 B dst row
    {
        float* o = out + dst * OUT_C + (sub & 1) * 8 + s2 * 4;
        float r0, r1, r2, r3;
        if (s2) { r0 = acc[4]; r1 = acc[5]; r2 = acc[6]; r3 = acc[7]; }
        else    { r0 = acc[0]; r1 = acc[1]; r2 = acc[2]; r3 = acc[3]; }
        asm volatile("red.global.add.v4.f32 [%0], {%1, %2, %3, %4};"
                     :: "l"(o), "f"(r0), "f"(r1), "f"(r2), "f"(r3)
                     : "memory");
    }

    // ---- echo streaming, riding the DRAM shadow ----
    if (g < 2 * N_EDGES) {
        if (echo & 1)
            out[N_NODES * OUT_C + g] = (float)__ldg(&ei[g]);
        if (echo & 2) {
            float4*       dst4 = (float4*)(out + N_NODES * OUT_C + 2 * N_EDGES);
            const float4* src4 = (const float4*)ea;
            dst4[g] = src4[g];
        }
    }
}

extern "C" void kernel_launch(void* const* d_in, const int* in_sizes, int n_in,
                              void* d_out, int out_size)
{
    const float* x     = (const float*)d_in[0];
    const int*   ei    = (const int*)  d_in[1];
    const float* ea    = (const float*)d_in[2];
    const float* w_nn  = (const float*)d_in[3];
    const float* b_nn  = (const float*)d_in[4];
    const float* root  = (const float*)d_in[5];
    const float* bias  = (const float*)d_in[6];
    float* out = (float*)d_out;

    int echo = 0;
    if (out_size >= N_NODES * OUT_C + 2 * N_EDGES)                        echo |= 1;
    if (out_size >= N_NODES * OUT_C + 2 * N_EDGES + N_EDGES * EDGE_F)     echo |= 2;

    // 50000 tasks (node-group x oq); 196 blocks x 256
    node_kernel<<<196, 256>>>(x, w_nn, b_nn, root, bias, out);
    edge_kernel<<<(N_EDGES * 4) / 256, 256>>>(ei, ea, out, echo);
}